// round 3
// baseline (speedup 1.0000x reference)
#include <cuda_runtime.h>
#include <math.h>

// Problem constants
#define Sv   512
#define Bv   64
#define FINv 512
#define Hv   512
#define G4   2048   // 4*H

// ---------------------------------------------------------------------------
// Scratch: precomputed input-gate term gx[t][b][col] = x_t[b]·W_ih[col] + bias
// 512*64*2048 floats = 268 MB, module-global (allocation-free at launch time).
// ---------------------------------------------------------------------------
__device__ float g_gx[(size_t)Sv * Bv * G4];

// Grid-barrier state (persists across launches; generation-based so leftover
// values from prior launches/replays are harmless).
__device__ unsigned int g_count = 0;
__device__ unsigned int g_gen   = 0;

// ===========================================================================
// Phase 1: gx = X[32768,512] @ W_ih^T[512,2048] + (b_ih + b_hh)
// Classic 128x128x16 fp32 tile, 256 threads, 8x8 microtile.
// ===========================================================================
#define BM 128
#define BN 128
#define BK 16
#define LPAD 132

__global__ __launch_bounds__(256, 2) void gemm_x_kernel(
    const float* __restrict__ X,     // [32768][512]  (m = t*64 + b)
    const float* __restrict__ W,     // [2048][512]
    const float* __restrict__ bih,
    const float* __restrict__ bhh)
{
    __shared__ float As[BK][LPAD];   // A transposed: As[k][m]
    __shared__ float Bs[BK][LPAD];   // B transposed: Bs[k][n]

    const int tid = threadIdx.x;
    const int m0  = blockIdx.y * BM;
    const int n0  = blockIdx.x * BN;
    const int tx  = tid & 15;        // n microtile index
    const int ty  = tid >> 4;        // m microtile index
    const int lr  = tid >> 2;        // load row (0..63), +64 for second half
    const int lc4 = (tid & 3) * 4;   // load k offset (float4)

    float acc[8][8];
#pragma unroll
    for (int i = 0; i < 8; i++)
#pragma unroll
        for (int j = 0; j < 8; j++) acc[i][j] = 0.f;

    for (int k0 = 0; k0 < FINv; k0 += BK) {
#pragma unroll
        for (int jj = 0; jj < 2; jj++) {
            int r = lr + 64 * jj;
            float4 av = *reinterpret_cast<const float4*>(
                X + (size_t)(m0 + r) * FINv + k0 + lc4);
            As[lc4 + 0][r] = av.x; As[lc4 + 1][r] = av.y;
            As[lc4 + 2][r] = av.z; As[lc4 + 3][r] = av.w;
            float4 bv = *reinterpret_cast<const float4*>(
                W + (size_t)(n0 + r) * FINv + k0 + lc4);
            Bs[lc4 + 0][r] = bv.x; Bs[lc4 + 1][r] = bv.y;
            Bs[lc4 + 2][r] = bv.z; Bs[lc4 + 3][r] = bv.w;
        }
        __syncthreads();
#pragma unroll
        for (int k = 0; k < BK; k++) {
            float a[8], b[8];
            *reinterpret_cast<float4*>(&a[0]) = *reinterpret_cast<const float4*>(&As[k][ty * 8]);
            *reinterpret_cast<float4*>(&a[4]) = *reinterpret_cast<const float4*>(&As[k][ty * 8 + 4]);
            *reinterpret_cast<float4*>(&b[0]) = *reinterpret_cast<const float4*>(&Bs[k][tx * 8]);
            *reinterpret_cast<float4*>(&b[4]) = *reinterpret_cast<const float4*>(&Bs[k][tx * 8 + 4]);
#pragma unroll
            for (int i = 0; i < 8; i++)
#pragma unroll
                for (int j = 0; j < 8; j++)
                    acc[i][j] += a[i] * b[j];
        }
        __syncthreads();
    }

    float bsum[8];
#pragma unroll
    for (int j = 0; j < 8; j++) {
        int n = n0 + tx * 8 + j;
        bsum[j] = bih[n] + bhh[n];
    }
#pragma unroll
    for (int i = 0; i < 8; i++) {
        size_t row = (size_t)(m0 + ty * 8 + i) * G4 + n0 + tx * 8;
        float4 v0 = make_float4(acc[i][0] + bsum[0], acc[i][1] + bsum[1],
                                acc[i][2] + bsum[2], acc[i][3] + bsum[3]);
        float4 v1 = make_float4(acc[i][4] + bsum[4], acc[i][5] + bsum[5],
                                acc[i][6] + bsum[6], acc[i][7] + bsum[7]);
        *reinterpret_cast<float4*>(&g_gx[row])     = v0;
        *reinterpret_cast<float4*>(&g_gx[row + 4]) = v1;
    }
}

// ===========================================================================
// Phase 2: persistent recurrence kernel.
// 128 blocks x 128 threads; block bx owns hidden units [4*bx, 4*bx+4) across
// all 4 gates (16 gate-columns) and all 64 batches. W_hh slice lives in smem
// for the whole kernel; h(t-1) is staged into smem per step from d_out (L2,
// via __ldcg); gx streamed from the 268MB scratch; grid-wide sense barrier
// between steps.
// ===========================================================================
#define NBLK 128
#define HPAD 516   // 512 + 4: float4-aligned rows, conflict-free compute reads

__global__ __launch_bounds__(128, 1) void lstm_rec_kernel(
    const float* __restrict__ whh,   // [2048][512]
    float* __restrict__ out)         // [S*B*H hs][S*B*H cs]
{
    extern __shared__ float sm[];
    float* w_s = sm;                       // [16][HPAD]
    float* h_s = sm + 16 * HPAD;           // [64][HPAD]
    float* ex  = sm + (16 + 64) * HPAD;    // [16][68] gate exchange

    float* hs_out = out;
    float* cs_out = out + (size_t)Sv * Bv * Hv;

    const int tid = threadIdx.x;
    const int u0  = blockIdx.x * 4;

    // Load W_hh slice: local col c (0..15) -> gate=c>>2, unit=c&3
    for (int i = tid; i < 16 * Hv; i += 128) {
        int c = i >> 9, k = i & (Hv - 1);
        int gr = ((c >> 2) * Hv) + u0 + (c & 3);
        w_s[c * HPAD + k] = whh[(size_t)gr * Hv + k];
    }

    unsigned bar_base = 0;
    if (tid == 0) bar_base = atomicAdd(&g_gen, 0u);   // stable leftover value

    const int col8 = tid & 7;   // this thread: gate-cols col8 and col8+8
    const int bg   = tid >> 3;  // batches bg, bg+16, bg+32, bg+48
    const float4* w0p = reinterpret_cast<const float4*>(w_s + col8 * HPAD);
    const float4* w1p = reinterpret_cast<const float4*>(w_s + (col8 + 8) * HPAD);
    const float4* hp4[4] = {
        reinterpret_cast<const float4*>(h_s + (size_t)(bg     ) * HPAD),
        reinterpret_cast<const float4*>(h_s + (size_t)(bg + 16) * HPAD),
        reinterpret_cast<const float4*>(h_s + (size_t)(bg + 32) * HPAD),
        reinterpret_cast<const float4*>(h_s + (size_t)(bg + 48) * HPAD)
    };

    __syncthreads();

    for (int t = 0; t < Sv; t++) {
        // ---- stage h(t-1) into smem ----
        if (t == 0) {
            for (int i = tid; i < 64 * HPAD; i += 128) h_s[i] = 0.f;
        } else {
            const float* hp = hs_out + (size_t)(t - 1) * Bv * Hv;
#pragma unroll 16
            for (int j = 0; j < 64; j++) {   // b = j, k4 = tid
                float4 v = __ldcg(reinterpret_cast<const float4*>(hp + (size_t)j * Hv) + tid);
                *reinterpret_cast<float4*>(h_s + (size_t)j * HPAD + 4 * tid) = v;
            }
        }

        // ---- prefetch gx terms + c(t-1) (latency hidden behind GEMM) ----
        float gxv[2][4];
        {
            const float* gxt = g_gx + (size_t)t * (Bv * G4);
#pragma unroll
            for (int ci = 0; ci < 2; ci++) {
                int c    = col8 + ci * 8;
                int gcol = ((c >> 2) * Hv) + u0 + (c & 3);
#pragma unroll
                for (int bj = 0; bj < 4; bj++)
                    gxv[ci][bj] = __ldg(gxt + (size_t)(bg + bj * 16) * G4 + gcol);
            }
        }
        float cpv[2];
        if (t > 0) {
            const float* cprev = cs_out + (size_t)(t - 1) * Bv * Hv;
#pragma unroll
            for (int r = 0; r < 2; r++) {
                int item = tid * 2 + r;
                cpv[r] = __ldcg(cprev + (size_t)(item & 63) * Hv + u0 + (item >> 6));
            }
        } else {
            cpv[0] = 0.f; cpv[1] = 0.f;
        }
        __syncthreads();

        // ---- recurrent GEMM: 2 cols x 4 batches per thread, K=512 ----
        float acc[2][4] = {{0.f, 0.f, 0.f, 0.f}, {0.f, 0.f, 0.f, 0.f}};
#pragma unroll 4
        for (int k4 = 0; k4 < Hv / 4; k4++) {
            float4 wa = w0p[k4];
            float4 wb = w1p[k4];
#pragma unroll
            for (int bj = 0; bj < 4; bj++) {
                float4 hv = hp4[bj][k4];
                acc[0][bj] += wa.x * hv.x; acc[0][bj] += wa.y * hv.y;
                acc[0][bj] += wa.z * hv.z; acc[0][bj] += wa.w * hv.w;
                acc[1][bj] += wb.x * hv.x; acc[1][bj] += wb.y * hv.y;
                acc[1][bj] += wb.z * hv.z; acc[1][bj] += wb.w * hv.w;
            }
        }

        // ---- exchange gates through smem ----
#pragma unroll
        for (int ci = 0; ci < 2; ci++) {
            int c = col8 + ci * 8;
#pragma unroll
            for (int bj = 0; bj < 4; bj++)
                ex[c * 68 + bg + bj * 16] = acc[ci][bj] + gxv[ci][bj];
        }
        __syncthreads();

        // ---- elementwise LSTM update: 2 (unit,batch) items per thread ----
        float* ht = hs_out + (size_t)t * Bv * Hv;
        float* ct = cs_out + (size_t)t * Bv * Hv;
#pragma unroll
        for (int r = 0; r < 2; r++) {
            int item = tid * 2 + r;
            int u = item >> 6, b = item & 63;
            float gi = ex[(0 + u)  * 68 + b];
            float gf = ex[(4 + u)  * 68 + b];
            float gg = ex[(8 + u)  * 68 + b];
            float go = ex[(12 + u) * 68 + b];
            float si = 1.f / (1.f + expf(-gi));
            float sf = 1.f / (1.f + expf(-gf));
            float so = 1.f / (1.f + expf(-go));
            float tg = tanhf(gg);
            float cc = sf * cpv[r] + si * tg;
            float hh = so * tanhf(cc);
            __stcg(ht + (size_t)b * Hv + u0 + u, hh);
            __stcg(ct + (size_t)b * Hv + u0 + u, cc);
        }

        // ---- grid barrier between steps (skip after last) ----
        if (t < Sv - 1) {
            __threadfence();
            __syncthreads();
            if (tid == 0) {
                unsigned target = bar_base + (unsigned)t + 1u;
                if (atomicAdd(&g_count, 1u) == NBLK - 1u) {
                    atomicExch(&g_count, 0u);
                    __threadfence();
                    atomicExch(&g_gen, target);   // release
                } else {
                    while ((int)(atomicAdd(&g_gen, 0u) - target) < 0) { }
                }
                __threadfence();
            }
            __syncthreads();
        }
    }
}

// ===========================================================================
// Launch
// ===========================================================================
extern "C" void kernel_launch(void* const* d_in, const int* in_sizes, int n_in,
                              void* d_out, int out_size)
{
    const float* seq  = (const float*)d_in[0];   // [512,64,512]
    const float* w_ih = (const float*)d_in[1];   // [2048,512]
    const float* w_hh = (const float*)d_in[2];   // [2048,512]
    const float* b_ih = (const float*)d_in[3];   // [2048]
    const float* b_hh = (const float*)d_in[4];   // [2048]
    float* out = (float*)d_out;                  // [2 * 512*64*512]

    const int smem_p2 = (16 * HPAD + 64 * HPAD + 16 * 68) * (int)sizeof(float); // 169472 B
    cudaFuncSetAttribute(lstm_rec_kernel,
                         cudaFuncAttributeMaxDynamicSharedMemorySize, smem_p2);

    dim3 g1(G4 / BN, (Sv * Bv) / BM);   // (16, 256)
    gemm_x_kernel<<<g1, 256>>>(seq, w_ih, b_ih, b_hh);
    lstm_rec_kernel<<<NBLK, 128, smem_p2>>>(w_hh, out);
}